// round 7
// baseline (speedup 1.0000x reference)
#include <cuda_runtime.h>
#include <cuda_bf16.h>

// ---------------------------------------------------------------------------
// IngredientPositionEncoding: segment-mean pooling + positional encoding.
//
// Kernel 1 (grid-stride over batch rows): warp-shuffle scan of separator
//   mask, emit packed int4 meta per output row (flat_start, cnt, s, 0).
//   Also resets the dynamic-work row counter.
// Kernel 2: persistent grid (888 blocks = 148 SM x 6), each WARP pulls rows
//   from a global atomic counter (perfect load balance, no wave-quantization
//   tail), software-pipelined meta prefetch, 5-deep float4 streaming loop.
// ---------------------------------------------------------------------------

#define MAX_SEPS_CAP 4096       // >= L
#define MAX_OUT_ROWS 65536      // >= B*max_ingr
#define PERSIST_BLOCKS 888      // 148 SMs * 6 blocks/SM (grid-stride safe anyway)

__device__ int4 g_seg_meta[MAX_OUT_ROWS];   // (flat_start, cnt, s, 0)
__device__ int  g_row_ctr;                  // dynamic work counter
__device__ int  g_fallback_max_ingr = 256;

// ---------------------------------------------------------------------------
// Kernel 1: segment boundaries. Grid-stride over batch rows. Resets counter.
// ---------------------------------------------------------------------------
__global__ void __launch_bounds__(256)
seg_bounds_kernel(const int* __restrict__ mask,
                  const int* __restrict__ max_ingr_ptr,
                  int BL, int OUT_ROWS,
                  int4* __restrict__ meta,
                  int* __restrict__ row_ctr)
{
    if (blockIdx.x == 0 && threadIdx.x == 0) *row_ctr = 0;

    const int max_ingr = *max_ingr_ptr;
    const int B = OUT_ROWS / max_ingr;
    const int L = BL / B;

    __shared__ int sh_sep[MAX_SEPS_CAP];
    __shared__ int sh_warp[9];

    const int tid  = threadIdx.x;
    const int lane = tid & 31;
    const int wid  = tid >> 5;
    const int nthr = blockDim.x;

    for (int b = blockIdx.x; b < B; b += gridDim.x) {
        const int* mrow = mask + b * L;
        const int chunk = (L + nthr - 1) / nthr;
        const int beg = tid * chunk;
        const int end = min(beg + chunk, L);

        // per-thread separator count (int4 fast path when aligned)
        int c = 0;
        if (((chunk & 3) == 0) && ((L & 3) == 0) && (beg < end)) {
            const int4* m4 = (const int4*)(mrow + beg);
            const int n4 = (end - beg) >> 2;
            for (int i = 0; i < n4; ++i) {
                int4 v = m4[i];
                c += (v.x != 0) + (v.y != 0) + (v.z != 0) + (v.w != 0);
            }
        } else {
            for (int i = beg; i < end; ++i) c += (mrow[i] != 0);
        }

        // warp inclusive scan
        int inc = c;
        #pragma unroll
        for (int o = 1; o < 32; o <<= 1) {
            int v = __shfl_up_sync(0xffffffffu, inc, o);
            if (lane >= o) inc += v;
        }
        if (lane == 31) sh_warp[wid] = inc;
        __syncthreads();

        if (tid == 0) {
            int acc = 0;
            #pragma unroll
            for (int w = 0; w < 8; ++w) { int t = sh_warp[w]; sh_warp[w] = acc; acc += t; }
            sh_warp[8] = acc;
        }
        __syncthreads();

        const int excl = inc - c + sh_warp[wid];
        const int nsep = sh_warp[8];

        int j = excl;
        for (int i = beg; i < end; ++i) {
            if (mrow[i] != 0) {
                if (j < MAX_SEPS_CAP) sh_sep[j] = i;
                ++j;
            }
        }
        __syncthreads();

        for (int s = tid; s < max_ingr; s += nthr) {
            int start, cnt;
            if (s < nsep) {
                start = (s == 0) ? 0 : (sh_sep[s - 1] + 1);
                cnt   = sh_sep[s] - start;
            } else if (s == nsep) {
                start = (nsep == 0) ? 0 : (sh_sep[nsep - 1] + 1);
                cnt   = L - start;
            } else {
                start = 0;
                cnt   = 0;
            }
            meta[b * max_ingr + s] = make_int4(b * L + start, cnt, s, 0);
        }
        __syncthreads();
    }
}

// ---------------------------------------------------------------------------
// Kernel 2 (fast path, D % 4 == 0): persistent warps pulling rows from a
// global counter; meta prefetched one row ahead; 5-deep float4 streaming.
// ---------------------------------------------------------------------------
__global__ void __launch_bounds__(256, 6)
seg_mean_v4_kernel(const float4* __restrict__ x4,
                   const float4* __restrict__ pe4,
                   const int4* __restrict__ meta,
                   float4* __restrict__ out4,
                   int D4, int OUT_ROWS,
                   int* __restrict__ row_ctr)
{
    const int lane = threadIdx.x & 31;

    // first row grab
    int r = 0;
    if (lane == 0) r = atomicAdd(row_ctr, 1);
    r = __shfl_sync(0xffffffffu, r, 0);
    if (r >= OUT_ROWS) return;
    int4 md = meta[r];

    while (true) {
        // prefetch next row id + meta (overlaps with current row's streaming)
        int rn = 0;
        if (lane == 0) rn = atomicAdd(row_ctr, 1);
        rn = __shfl_sync(0xffffffffu, rn, 0);
        int4 mdn = make_int4(0, 0, 0, 0);
        if (rn < OUT_ROWS) mdn = meta[rn];

        // process current row
        const int start = md.x;
        const int cnt   = md.y;
        const int s     = md.z;
        const float inv = (cnt > 0) ? (1.0f / (float)cnt) : 0.0f;

        for (int c = lane; c < D4; c += 32) {
            const float4* __restrict__ xp = x4 + start * D4 + c;
            float4 acc = {0.f, 0.f, 0.f, 0.f};
            int t = 0;
            // 5-deep unroll: cnt=15 -> exactly 3 iterations, no tail
            for (; t + 5 <= cnt; t += 5) {
                float4 v0 = __ldcs(xp);
                float4 v1 = __ldcs(xp + D4);
                float4 v2 = __ldcs(xp + 2 * D4);
                float4 v3 = __ldcs(xp + 3 * D4);
                float4 v4 = __ldcs(xp + 4 * D4);
                xp += 5 * D4;
                acc.x += ((v0.x + v1.x) + (v2.x + v3.x)) + v4.x;
                acc.y += ((v0.y + v1.y) + (v2.y + v3.y)) + v4.y;
                acc.z += ((v0.z + v1.z) + (v2.z + v3.z)) + v4.z;
                acc.w += ((v0.w + v1.w) + (v2.w + v3.w)) + v4.w;
            }
            for (; t < cnt; ++t) {
                float4 v = __ldcs(xp);
                xp += D4;
                acc.x += v.x; acc.y += v.y; acc.z += v.z; acc.w += v.w;
            }

            float4 p = pe4[s * D4 + c];
            float4 o;
            o.x = acc.x * inv + p.x;
            o.y = acc.y * inv + p.y;
            o.z = acc.z * inv + p.z;
            o.w = acc.w * inv + p.w;
            out4[r * D4 + c] = o;
        }

        if (rn >= OUT_ROWS) return;
        r = rn;
        md = mdn;
    }
}

// ---------------------------------------------------------------------------
// Kernel 2 (generic fallback, any D): one block per row, thread = channel.
// ---------------------------------------------------------------------------
__global__ void seg_mean_scalar_kernel(const float* __restrict__ x,
                                       const float* __restrict__ pe,
                                       const int4* __restrict__ meta,
                                       float* __restrict__ out,
                                       int D)
{
    const int r = blockIdx.x;
    const int4 md = meta[r];
    const int start = md.x;
    const int cnt   = md.y;
    const int s     = md.z;
    const float inv = (cnt > 0) ? (1.0f / (float)cnt) : 0.0f;

    for (int d = threadIdx.x; d < D; d += blockDim.x) {
        const float* xp = x + (long long)start * D + d;
        float a0 = 0.f, a1 = 0.f, a2 = 0.f, a3 = 0.f;
        int t = 0;
        for (; t + 4 <= cnt; t += 4) {
            a0 += xp[(long long)(t + 0) * D];
            a1 += xp[(long long)(t + 1) * D];
            a2 += xp[(long long)(t + 2) * D];
            a3 += xp[(long long)(t + 3) * D];
        }
        for (; t < cnt; ++t) a0 += xp[(long long)t * D];
        float sum = (a0 + a1) + (a2 + a3);
        out[(long long)r * D + d] = sum * inv + pe[(long long)s * D + d];
    }
}

// ---------------------------------------------------------------------------
// Launch
// ---------------------------------------------------------------------------
extern "C" void kernel_launch(void* const* d_in, const int* in_sizes, int n_in,
                              void* d_out, int out_size)
{
    const float* x    = (const float*)d_in[0];
    const int*   mask = (const int*)d_in[1];
    const float* pe   = (const float*)d_in[2];

    const int* max_ingr_ptr;
    if (n_in >= 4) {
        max_ingr_ptr = (const int*)d_in[3];
    } else {
        int* p = nullptr;
        cudaGetSymbolAddress((void**)&p, g_fallback_max_ingr);
        max_ingr_ptr = p;
    }

    const int x_size    = in_sizes[0];            // B*L*D
    const int mask_size = in_sizes[1];            // B*L
    const int D         = x_size / mask_size;     // 128
    const int OUT_ROWS  = out_size / D;           // B*max_ingr

    int4* meta_p = nullptr;
    int*  ctr_p  = nullptr;
    cudaGetSymbolAddress((void**)&meta_p, g_seg_meta);
    cudaGetSymbolAddress((void**)&ctr_p,  g_row_ctr);

    // Kernel 1: grid-stride over batch rows; also resets the row counter.
    seg_bounds_kernel<<<256, 256>>>(mask, max_ingr_ptr,
                                    mask_size, OUT_ROWS, meta_p, ctr_p);

    if ((D & 3) == 0) {
        const int D4 = D >> 2;
        seg_mean_v4_kernel<<<PERSIST_BLOCKS, 256>>>(
            (const float4*)x, (const float4*)pe, meta_p,
            (float4*)d_out, D4, OUT_ROWS, ctr_p);
    } else {
        seg_mean_scalar_kernel<<<OUT_ROWS, 128>>>(
            x, pe, meta_p, (float*)d_out, D);
    }
}

// round 8
// speedup vs baseline: 1.1971x; 1.1971x over previous
#include <cuda_runtime.h>
#include <cuda_bf16.h>

// ---------------------------------------------------------------------------
// IngredientPositionEncoding: segment-mean pooling + positional encoding.
//
// Kernel 1 (grid-stride over batch rows): warp-shuffle scan of separator
//   mask, emit packed int4 meta per output row (flat_start, cnt, s, 0).
// Kernel 2: single-wave static-interleave persistent kernel. 296 blocks
//   (148 SMs x 2) x 8 warps = 2368 warps; warp g processes rows
//   g, g+2368, ... (rows/warp = 6.92 -> 1.2% quantization tail, no atomics).
//   Next row's meta is prefetched while the current row streams.
// ---------------------------------------------------------------------------

#define MAX_SEPS_CAP 4096       // >= L
#define MAX_OUT_ROWS 65536      // >= B*max_ingr
#define P_BLOCKS 296            // 148 SMs * 2 blocks (single wave)
#define P_WARPS  (P_BLOCKS * 8) // 2368 warps

__device__ int4 g_seg_meta[MAX_OUT_ROWS];   // (flat_start, cnt, s, 0)
__device__ int  g_fallback_max_ingr = 256;

// ---------------------------------------------------------------------------
// Kernel 1: segment boundaries. Grid-stride over batch rows.
// ---------------------------------------------------------------------------
__global__ void __launch_bounds__(256)
seg_bounds_kernel(const int* __restrict__ mask,
                  const int* __restrict__ max_ingr_ptr,
                  int BL, int OUT_ROWS,
                  int4* __restrict__ meta)
{
    const int max_ingr = *max_ingr_ptr;
    const int B = OUT_ROWS / max_ingr;
    const int L = BL / B;

    __shared__ int sh_sep[MAX_SEPS_CAP];
    __shared__ int sh_warp[9];

    const int tid  = threadIdx.x;
    const int lane = tid & 31;
    const int wid  = tid >> 5;
    const int nthr = blockDim.x;

    for (int b = blockIdx.x; b < B; b += gridDim.x) {
        const int* mrow = mask + b * L;
        const int chunk = (L + nthr - 1) / nthr;
        const int beg = tid * chunk;
        const int end = min(beg + chunk, L);

        // per-thread separator count (int4 fast path when aligned)
        int c = 0;
        if (((chunk & 3) == 0) && ((L & 3) == 0) && (beg < end)) {
            const int4* m4 = (const int4*)(mrow + beg);
            const int n4 = (end - beg) >> 2;
            for (int i = 0; i < n4; ++i) {
                int4 v = m4[i];
                c += (v.x != 0) + (v.y != 0) + (v.z != 0) + (v.w != 0);
            }
        } else {
            for (int i = beg; i < end; ++i) c += (mrow[i] != 0);
        }

        // warp inclusive scan
        int inc = c;
        #pragma unroll
        for (int o = 1; o < 32; o <<= 1) {
            int v = __shfl_up_sync(0xffffffffu, inc, o);
            if (lane >= o) inc += v;
        }
        if (lane == 31) sh_warp[wid] = inc;
        __syncthreads();

        if (tid == 0) {
            int acc = 0;
            #pragma unroll
            for (int w = 0; w < 8; ++w) { int t = sh_warp[w]; sh_warp[w] = acc; acc += t; }
            sh_warp[8] = acc;
        }
        __syncthreads();

        const int excl = inc - c + sh_warp[wid];
        const int nsep = sh_warp[8];

        int j = excl;
        for (int i = beg; i < end; ++i) {
            if (mrow[i] != 0) {
                if (j < MAX_SEPS_CAP) sh_sep[j] = i;
                ++j;
            }
        }
        __syncthreads();

        for (int s = tid; s < max_ingr; s += nthr) {
            int start, cnt;
            if (s < nsep) {
                start = (s == 0) ? 0 : (sh_sep[s - 1] + 1);
                cnt   = sh_sep[s] - start;
            } else if (s == nsep) {
                start = (nsep == 0) ? 0 : (sh_sep[nsep - 1] + 1);
                cnt   = L - start;
            } else {
                start = 0;
                cnt   = 0;
            }
            meta[b * max_ingr + s] = make_int4(b * L + start, cnt, s, 0);
        }
        __syncthreads();
    }
}

// ---------------------------------------------------------------------------
// Kernel 2 (fast path, D % 4 == 0): static-interleave persistent warps,
// meta prefetched one row ahead, 5-deep float4 streaming loads.
// ---------------------------------------------------------------------------
__global__ void __launch_bounds__(256)
seg_mean_v4_kernel(const float4* __restrict__ x4,
                   const float4* __restrict__ pe4,
                   const int4* __restrict__ meta,
                   float4* __restrict__ out4,
                   int D4, int OUT_ROWS)
{
    const int lane = threadIdx.x & 31;
    const int wgid = blockIdx.x * (blockDim.x >> 5) + (threadIdx.x >> 5);
    const int step = gridDim.x * (blockDim.x >> 5);

    int r = wgid;
    if (r >= OUT_ROWS) return;
    int4 md = meta[r];

    while (true) {
        // prefetch next row's meta (address known statically -> no atomics)
        const int rn = r + step;
        int4 mdn;
        if (rn < OUT_ROWS) mdn = meta[rn];

        const int start = md.x;
        const int cnt   = md.y;
        const int s     = md.z;
        const float inv = (cnt > 0) ? (1.0f / (float)cnt) : 0.0f;

        for (int c = lane; c < D4; c += 32) {
            const float4* __restrict__ xp = x4 + start * D4 + c;
            float4 acc = {0.f, 0.f, 0.f, 0.f};
            int t = 0;
            // 5-deep unroll: cnt=15 -> exactly 3 iterations, no tail
            for (; t + 5 <= cnt; t += 5) {
                float4 v0 = __ldcs(xp);
                float4 v1 = __ldcs(xp + D4);
                float4 v2 = __ldcs(xp + 2 * D4);
                float4 v3 = __ldcs(xp + 3 * D4);
                float4 v4 = __ldcs(xp + 4 * D4);
                xp += 5 * D4;
                acc.x += ((v0.x + v1.x) + (v2.x + v3.x)) + v4.x;
                acc.y += ((v0.y + v1.y) + (v2.y + v3.y)) + v4.y;
                acc.z += ((v0.z + v1.z) + (v2.z + v3.z)) + v4.z;
                acc.w += ((v0.w + v1.w) + (v2.w + v3.w)) + v4.w;
            }
            for (; t < cnt; ++t) {
                float4 v = __ldcs(xp);
                xp += D4;
                acc.x += v.x; acc.y += v.y; acc.z += v.z; acc.w += v.w;
            }

            float4 p = pe4[s * D4 + c];
            float4 o;
            o.x = acc.x * inv + p.x;
            o.y = acc.y * inv + p.y;
            o.z = acc.z * inv + p.z;
            o.w = acc.w * inv + p.w;
            out4[r * D4 + c] = o;
        }

        if (rn >= OUT_ROWS) return;
        r = rn;
        md = mdn;
    }
}

// ---------------------------------------------------------------------------
// Kernel 2 (generic fallback, any D): one block per row, thread = channel.
// ---------------------------------------------------------------------------
__global__ void seg_mean_scalar_kernel(const float* __restrict__ x,
                                       const float* __restrict__ pe,
                                       const int4* __restrict__ meta,
                                       float* __restrict__ out,
                                       int D)
{
    const int r = blockIdx.x;
    const int4 md = meta[r];
    const int start = md.x;
    const int cnt   = md.y;
    const int s     = md.z;
    const float inv = (cnt > 0) ? (1.0f / (float)cnt) : 0.0f;

    for (int d = threadIdx.x; d < D; d += blockDim.x) {
        const float* xp = x + (long long)start * D + d;
        float a0 = 0.f, a1 = 0.f, a2 = 0.f, a3 = 0.f;
        int t = 0;
        for (; t + 4 <= cnt; t += 4) {
            a0 += xp[(long long)(t + 0) * D];
            a1 += xp[(long long)(t + 1) * D];
            a2 += xp[(long long)(t + 2) * D];
            a3 += xp[(long long)(t + 3) * D];
        }
        for (; t < cnt; ++t) a0 += xp[(long long)t * D];
        float sum = (a0 + a1) + (a2 + a3);
        out[(long long)r * D + d] = sum * inv + pe[(long long)s * D + d];
    }
}

// ---------------------------------------------------------------------------
// Launch
// ---------------------------------------------------------------------------
extern "C" void kernel_launch(void* const* d_in, const int* in_sizes, int n_in,
                              void* d_out, int out_size)
{
    const float* x    = (const float*)d_in[0];
    const int*   mask = (const int*)d_in[1];
    const float* pe   = (const float*)d_in[2];

    const int* max_ingr_ptr;
    if (n_in >= 4) {
        max_ingr_ptr = (const int*)d_in[3];
    } else {
        int* p = nullptr;
        cudaGetSymbolAddress((void**)&p, g_fallback_max_ingr);
        max_ingr_ptr = p;
    }

    const int x_size    = in_sizes[0];            // B*L*D
    const int mask_size = in_sizes[1];            // B*L
    const int D         = x_size / mask_size;     // 128
    const int OUT_ROWS  = out_size / D;           // B*max_ingr

    int4* meta_p = nullptr;
    cudaGetSymbolAddress((void**)&meta_p, g_seg_meta);

    // Kernel 1: grid-stride over batch rows (B resolved on-device).
    seg_bounds_kernel<<<256, 256>>>(mask, max_ingr_ptr,
                                    mask_size, OUT_ROWS, meta_p);

    if ((D & 3) == 0) {
        const int D4 = D >> 2;
        seg_mean_v4_kernel<<<P_BLOCKS, 256>>>(
            (const float4*)x, (const float4*)pe, meta_p,
            (float4*)d_out, D4, OUT_ROWS);
    } else {
        seg_mean_scalar_kernel<<<OUT_ROWS, 128>>>(
            x, pe, meta_p, (float*)d_out, D);
    }
}